// round 1
// baseline (speedup 1.0000x reference)
#include <cuda_runtime.h>

// Problem constants (fixed by the dataset)
constexpr int N_NODES = 50000;
constexpr int E_EDGES = 800000;
constexpr int IN_DIM  = 128;
constexpr int OUT_DIM = 128;
constexpr int R_REL   = 8;
constexpr int K_DIM   = IN_DIM * (R_REL + 1);   // 1152 (self + 8 relations)

// Scratch: per-(relation,node) feature sums and degree counts.
// __device__ globals (no allocation allowed in kernel_launch).
__device__ float g_agg[(size_t)R_REL * N_NODES * IN_DIM];   // 204.8 MB
__device__ float g_deg[(size_t)R_REL * N_NODES];            // 1.6 MB

// ---------------------------------------------------------------------------
// Kernel 1: zero the scratch buffers
// ---------------------------------------------------------------------------
__global__ void zero_kernel() {
    const size_t total4 = ((size_t)R_REL * N_NODES * IN_DIM) / 4;
    const size_t i      = (size_t)blockIdx.x * blockDim.x + threadIdx.x;
    const size_t stride = (size_t)gridDim.x * blockDim.x;
    float4* agg4 = reinterpret_cast<float4*>(g_agg);
    const float4 z = make_float4(0.f, 0.f, 0.f, 0.f);
    for (size_t j = i; j < total4; j += stride) agg4[j] = z;
    for (size_t j = i; j < (size_t)R_REL * N_NODES; j += stride) g_deg[j] = 0.f;
}

// ---------------------------------------------------------------------------
// Kernel 2: scatter raw features into agg[et, dst] for both edge directions.
// One warp per directed edge; lane l handles floats [4l, 4l+4).
// Uses red.global.add.v4.f32 (vectorized fire-and-forget atomic).
// ---------------------------------------------------------------------------
__global__ void scatter_kernel(const float* __restrict__ x,
                               const int*   __restrict__ ei,
                               const int*   __restrict__ et) {
    const unsigned gtid = blockIdx.x * (unsigned)blockDim.x + threadIdx.x;
    const int w    = (int)(gtid >> 5);
    const int lane = threadIdx.x & 31;
    if (w >= 2 * E_EDGES) return;

    int e, src, dst;
    if (w < E_EDGES) {            // original direction
        e = w;
        src = ei[e];
        dst = ei[E_EDGES + e];
    } else {                      // symmetrized (reverse) direction
        e = w - E_EDGES;
        src = ei[E_EDGES + e];
        dst = ei[e];
    }
    const int r = et[e];

    const float4 v = *reinterpret_cast<const float4*>(
        x + (size_t)src * IN_DIM + lane * 4);

    float* p = g_agg + ((size_t)r * N_NODES + dst) * IN_DIM + lane * 4;
    asm volatile("red.global.add.v4.f32 [%0], {%1, %2, %3, %4};"
                 :: "l"(p), "f"(v.x), "f"(v.y), "f"(v.z), "f"(v.w)
                 : "memory");

    if (lane == 0) atomicAdd(g_deg + (size_t)r * N_NODES + dst, 1.0f);
}

// ---------------------------------------------------------------------------
// Kernel 3: out = H @ W
//   H[v, k] = k<128 ? x[v,k] : deg_inv(r,v) * agg[r, v, k%128]   (r = k/128-1)
//   W[k, j] = k<128 ? self_weight[k,j] : weight[r, k%128, j]
// 128x128x16 smem-tiled SGEMM, 8x8 per-thread microtile, packed f32x2 FMAs.
// ---------------------------------------------------------------------------
__device__ __forceinline__ unsigned long long pack2(float lo, float hi) {
    unsigned long long r;
    asm("mov.b64 %0, {%1, %2};" : "=l"(r) : "f"(lo), "f"(hi));
    return r;
}
__device__ __forceinline__ void unpack2(unsigned long long v, float& lo, float& hi) {
    asm("mov.b64 {%0, %1}, %2;" : "=f"(lo), "=f"(hi) : "l"(v));
}
__device__ __forceinline__ void ffma2(unsigned long long& d,
                                      unsigned long long a,
                                      unsigned long long b) {
    asm("fma.rn.f32x2 %0, %1, %2, %0;" : "+l"(d) : "l"(a), "l"(b));
}

__global__ __launch_bounds__(256, 2)
void gemm_kernel(const float* __restrict__ x,
                 const float* __restrict__ weight,   // [R*128, 128]
                 const float* __restrict__ selfw,    // [128, 128]
                 float* __restrict__ out) {
    constexpr int BM = 128, BK = 16;
    __shared__ float              As[BK][BM];        // A tile, transposed
    __shared__ unsigned long long Bs[BK][OUT_DIM/2]; // B tile, pre-packed pairs

    const int tid = threadIdx.x;
    const int m0  = blockIdx.x * BM;

    // A-load mapping: thread -> (row am, 8 consecutive k at offset ak)
    const int  am     = tid >> 1;          // 0..127
    const int  ak     = (tid & 1) * 8;     // 0 or 8
    const int  mg     = m0 + am;
    const bool mvalid = (mg < N_NODES);

    // B-load mapping: thread -> (k row bk, 8 consecutive cols at bj)
    const int bk = tid >> 4;               // 0..15
    const int bj = (tid & 15) * 8;         // 0..120

    // Compute mapping: 16x16 thread grid, 8x8 microtile each
    const int tx = tid & 15;
    const int ty = tid >> 4;

    unsigned long long acc[8][4];
    #pragma unroll
    for (int i = 0; i < 8; i++)
        #pragma unroll
        for (int j = 0; j < 4; j++) acc[i][j] = 0ull;

    for (int k0 = 0; k0 < K_DIM; k0 += BK) {
        // ---- global loads (A with fused deg_inv scaling) ----
        float4 a0 = make_float4(0.f, 0.f, 0.f, 0.f);
        float4 a1 = a0;
        if (mvalid) {
            const float* aptr;
            float scale;
            if (k0 < IN_DIM) {
                aptr  = x + (size_t)mg * IN_DIM + (k0 + ak);
                scale = 1.0f;
            } else {
                const int r  = (k0 - IN_DIM) >> 7;
                const int i0 = (k0 - IN_DIM) & 127;
                aptr = g_agg + ((size_t)r * N_NODES + mg) * IN_DIM + (i0 + ak);
                const float d = g_deg[(size_t)r * N_NODES + mg];
                scale = (d > 0.f) ? (1.0f / d) : 0.0f;
            }
            a0 = *reinterpret_cast<const float4*>(aptr);
            a1 = *reinterpret_cast<const float4*>(aptr + 4);
            a0.x *= scale; a0.y *= scale; a0.z *= scale; a0.w *= scale;
            a1.x *= scale; a1.y *= scale; a1.z *= scale; a1.w *= scale;
        }
        const float* bsrc = (k0 < IN_DIM)
            ? (selfw  + (size_t)(k0 + bk) * OUT_DIM + bj)
            : (weight + (size_t)(k0 - IN_DIM + bk) * OUT_DIM + bj);
        const float4 b0 = *reinterpret_cast<const float4*>(bsrc);
        const float4 b1 = *reinterpret_cast<const float4*>(bsrc + 4);

        __syncthreads();   // protect previous iteration's smem reads
        As[ak + 0][am] = a0.x; As[ak + 1][am] = a0.y;
        As[ak + 2][am] = a0.z; As[ak + 3][am] = a0.w;
        As[ak + 4][am] = a1.x; As[ak + 5][am] = a1.y;
        As[ak + 6][am] = a1.z; As[ak + 7][am] = a1.w;
        const int bw = bj >> 1;
        Bs[bk][bw + 0] = pack2(b0.x, b0.y);
        Bs[bk][bw + 1] = pack2(b0.z, b0.w);
        Bs[bk][bw + 2] = pack2(b1.x, b1.y);
        Bs[bk][bw + 3] = pack2(b1.z, b1.w);
        __syncthreads();

        // ---- microkernel: 16 k-steps of 8x8 (as 8x4 packed-pair) FMAs ----
        #pragma unroll
        for (int kk = 0; kk < BK; kk++) {
            unsigned long long aa[8];
            #pragma unroll
            for (int i = 0; i < 8; i++) {
                const float av = As[kk][ty * 8 + i];
                aa[i] = pack2(av, av);
            }
            unsigned long long bb[4];
            #pragma unroll
            for (int j = 0; j < 4; j++) bb[j] = Bs[kk][tx * 4 + j];
            #pragma unroll
            for (int i = 0; i < 8; i++)
                #pragma unroll
                for (int j = 0; j < 4; j++)
                    ffma2(acc[i][j], aa[i], bb[j]);
        }
    }

    // ---- epilogue ----
    #pragma unroll
    for (int i = 0; i < 8; i++) {
        const int row = m0 + ty * 8 + i;
        if (row >= N_NODES) continue;
        float o[8];
        #pragma unroll
        for (int j = 0; j < 4; j++) unpack2(acc[i][j], o[2 * j], o[2 * j + 1]);
        float4* op = reinterpret_cast<float4*>(out + (size_t)row * OUT_DIM + tx * 8);
        op[0] = make_float4(o[0], o[1], o[2], o[3]);
        op[1] = make_float4(o[4], o[5], o[6], o[7]);
    }
}

// ---------------------------------------------------------------------------
// Launch
// Inputs (metadata order): x[50000,128] f32, weight[8,128,128] f32,
//   self_weight[128,128] f32, edge_index[2,800000] i32, edge_type[800000] i32
// Output: [50000,128] f32
// ---------------------------------------------------------------------------
extern "C" void kernel_launch(void* const* d_in, const int* in_sizes, int n_in,
                              void* d_out, int out_size) {
    const float* x      = (const float*)d_in[0];
    const float* weight = (const float*)d_in[1];
    const float* selfw  = (const float*)d_in[2];
    const int*   ei     = (const int*)d_in[3];
    const int*   et     = (const int*)d_in[4];
    float*       out    = (float*)d_out;

    zero_kernel<<<2048, 256>>>();

    const int warps   = 2 * E_EDGES;                   // 1.6M directed edges
    const int threads = 256;
    const int blocks  = (warps * 32 + threads - 1) / threads;  // 200000
    scatter_kernel<<<blocks, threads>>>(x, ei, et);

    gemm_kernel<<<(N_NODES + 127) / 128, 256>>>(x, weight, selfw, out);
}

// round 3
// speedup vs baseline: 1.2104x; 1.2104x over previous
#include <cuda_runtime.h>
#include <cuda_bf16.h>
#include <cstdint>

// Problem constants
constexpr int N_NODES = 50000;
constexpr int E_EDGES = 800000;
constexpr int IN_DIM  = 128;
constexpr int OUT_DIM = 128;
constexpr int R_REL   = 8;
constexpr int K_DIM   = IN_DIM * (R_REL + 1);   // 1152
constexpr int KC      = 64;                      // K per chunk
constexpr int NCHUNK  = K_DIM / KC;              // 18

// Scratch (__device__ globals; no allocation allowed)
__device__ float g_agg[(size_t)R_REL * N_NODES * IN_DIM];   // 204.8 MB
__device__ float g_deg[(size_t)R_REL * N_NODES];            // 1.6 MB
__device__ __nv_bfloat16 g_bt_hi[(size_t)OUT_DIM * K_DIM];  // W^T hi  [128,1152]
__device__ __nv_bfloat16 g_bt_lo[(size_t)OUT_DIM * K_DIM];  // W^T lo

// ---------------------------------------------------------------------------
// Kernel 1: zero scratch
// ---------------------------------------------------------------------------
__global__ void zero_kernel() {
    const size_t total4 = ((size_t)R_REL * N_NODES * IN_DIM) / 4;
    const size_t i      = (size_t)blockIdx.x * blockDim.x + threadIdx.x;
    const size_t stride = (size_t)gridDim.x * blockDim.x;
    float4* agg4 = reinterpret_cast<float4*>(g_agg);
    const float4 z = make_float4(0.f, 0.f, 0.f, 0.f);
    for (size_t j = i; j < total4; j += stride) agg4[j] = z;
    for (size_t j = i; j < (size_t)R_REL * N_NODES; j += stride) g_deg[j] = 0.f;
}

// ---------------------------------------------------------------------------
// Kernel 2: W^T split into bf16 hi/lo.  BT[n][k] = Wcat[k][n]
// ---------------------------------------------------------------------------
__global__ void convert_w_kernel(const float* __restrict__ weight,
                                 const float* __restrict__ selfw) {
    const int idx = blockIdx.x * blockDim.x + threadIdx.x;
    if (idx >= OUT_DIM * K_DIM) return;
    const int n = idx / K_DIM;
    const int k = idx % K_DIM;
    const float v = (k < IN_DIM)
        ? selfw[(size_t)k * OUT_DIM + n]
        : weight[(size_t)(k - IN_DIM) * OUT_DIM + n];
    const __nv_bfloat16 hi = __float2bfloat16(v);
    const __nv_bfloat16 lo = __float2bfloat16(v - __bfloat162float(hi));
    g_bt_hi[idx] = hi;
    g_bt_lo[idx] = lo;
}

// ---------------------------------------------------------------------------
// Kernel 3: scatter raw features into agg[et, dst], both directions.
// ---------------------------------------------------------------------------
__global__ void scatter_kernel(const float* __restrict__ x,
                               const int*   __restrict__ ei,
                               const int*   __restrict__ et) {
    const unsigned gtid = blockIdx.x * (unsigned)blockDim.x + threadIdx.x;
    const int w    = (int)(gtid >> 5);
    const int lane = threadIdx.x & 31;
    if (w >= 2 * E_EDGES) return;

    int e, src, dst;
    if (w < E_EDGES) {
        e = w;  src = ei[e];            dst = ei[E_EDGES + e];
    } else {
        e = w - E_EDGES;  src = ei[E_EDGES + e];  dst = ei[e];
    }
    const int r = et[e];

    const float4 v = *reinterpret_cast<const float4*>(
        x + (size_t)src * IN_DIM + lane * 4);

    float* p = g_agg + ((size_t)r * N_NODES + dst) * IN_DIM + lane * 4;
    asm volatile("red.global.add.v4.f32 [%0], {%1, %2, %3, %4};"
                 :: "l"(p), "f"(v.x), "f"(v.y), "f"(v.z), "f"(v.w)
                 : "memory");

    if (lane == 0) atomicAdd(g_deg + (size_t)r * N_NODES + dst, 1.0f);
}

// ---------------------------------------------------------------------------
// mma.sync helpers (family-common: compile under plain compute_103)
// ---------------------------------------------------------------------------
__device__ __forceinline__ uint32_t smem_u32(const void* p) {
    uint32_t a;
    asm("{ .reg .u64 t; cvta.to.shared.u64 t, %1; cvt.u32.u64 %0, t; }"
        : "=r"(a) : "l"(p));
    return a;
}
__device__ __forceinline__ uint32_t sw128(uint32_t o) {
    return o ^ ((o >> 3) & 0x70);
}
__device__ __forceinline__ void ldsm_x4(uint32_t addr,
                                        uint32_t& r0, uint32_t& r1,
                                        uint32_t& r2, uint32_t& r3) {
    asm volatile("ldmatrix.sync.aligned.m8n8.x4.shared.b16 {%0,%1,%2,%3}, [%4];"
                 : "=r"(r0), "=r"(r1), "=r"(r2), "=r"(r3) : "r"(addr));
}
__device__ __forceinline__ void mma16816(float* c, const uint32_t* a,
                                         uint32_t b0, uint32_t b1) {
    asm volatile(
        "mma.sync.aligned.m16n8k16.row.col.f32.bf16.bf16.f32 "
        "{%0,%1,%2,%3}, {%4,%5,%6,%7}, {%8,%9}, {%0,%1,%2,%3};"
        : "+f"(c[0]), "+f"(c[1]), "+f"(c[2]), "+f"(c[3])
        : "r"(a[0]), "r"(a[1]), "r"(a[2]), "r"(a[3]), "r"(b0), "r"(b1));
}

// Dynamic smem layout: four 16KB tiles (128 rows x 128B, SW128-swizzled)
constexpr int OFF_AHI = 0;
constexpr int OFF_ALO = 16384;
constexpr int OFF_BHI = 32768;
constexpr int OFF_BLO = 49152;
constexpr int SMEM_TOTAL = 65536;

// ---------------------------------------------------------------------------
// Kernel 4: out = H @ Wcat  (bf16 3-split via mma.sync.m16n8k16)
//   H[v,k] = k<128 ? x[v,k] : deg_inv(r,v)*agg[r,v,k&127]
// CTA: 128x128 output; 8 warps in 4x2 grid, each warp 32x64.
// ---------------------------------------------------------------------------
__global__ __launch_bounds__(256)
void gemm_kernel(const float* __restrict__ x, float* __restrict__ out) {
    extern __shared__ char smem[];
    const uint32_t sb = smem_u32(smem);
    const int tid  = threadIdx.x;
    const int wid  = tid >> 5;
    const int lane = tid & 31;
    const int m0   = blockIdx.x * 128;

    // warp tiling: 4 (m) x 2 (n)
    const int wm = wid & 3;          // 0..3 -> rows wm*32
    const int wn = wid >> 2;         // 0..1 -> cols wn*64
    const int mbase = wm * 32;
    const int nbase = wn * 64;

    // per-lane ldmatrix address components (same pattern for A and B)
    const int rlane = lane & 15;          // row within 16-row group
    const int klane = (lane >> 4) * 16;   // byte offset within 32B k-slice

    // A-load mapping: 2 threads per row, 32 floats each
    const int  arow = tid >> 1;
    const int  aseg = tid & 1;
    const int  mg   = m0 + arow;
    const bool av   = (mg < N_NODES);

    // B-load mapping: threads 0-127 -> hi, 128-255 -> lo; row n = tid&127
    const int bbuf = tid >> 7;
    const int bn   = tid & 127;
    const __nv_bfloat16* bsrc = (bbuf ? g_bt_lo : g_bt_hi) + (size_t)bn * K_DIM;
    const int boff = bbuf ? OFF_BLO : OFF_BHI;

    float acc[2][8][4];   // [m-group 16][n-tile 8][frag]
    #pragma unroll
    for (int i = 0; i < 2; i++)
        #pragma unroll
        for (int j = 0; j < 8; j++)
            #pragma unroll
            for (int q = 0; q < 4; q++) acc[i][j][q] = 0.f;

    for (int ch = 0; ch < NCHUNK; ch++) {
        // ---- global loads ----
        float4 va[8];
        float  sc = 0.f;
        if (av) {
            const float* ap;
            if (ch < 2) {
                ap = x + (size_t)mg * IN_DIM + ch * 64;
                sc = 1.0f;
            } else {
                const int r  = (ch - 2) >> 1;
                const int ko = ((ch - 2) & 1) * 64;
                ap = g_agg + ((size_t)r * N_NODES + mg) * IN_DIM + ko;
                const float d = g_deg[(size_t)r * N_NODES + mg];
                sc = (d > 0.f) ? (1.0f / d) : 0.0f;
            }
            #pragma unroll
            for (int i = 0; i < 8; i++)
                va[i] = *reinterpret_cast<const float4*>(ap + aseg * 32 + i * 4);
        } else {
            #pragma unroll
            for (int i = 0; i < 8; i++) va[i] = make_float4(0.f, 0.f, 0.f, 0.f);
        }
        uint4 vb[8];
        const uint4* bp = reinterpret_cast<const uint4*>(bsrc + ch * KC);
        #pragma unroll
        for (int u = 0; u < 8; u++) vb[u] = bp[u];

        __syncthreads();   // previous chunk's consumers are done with smem

        // ---- store A (scaled, hi/lo split), SW128 ----
        #pragma unroll
        for (int i = 0; i < 8; i++) {
            float f0 = va[i].x * sc, f1 = va[i].y * sc,
                  f2 = va[i].z * sc, f3 = va[i].w * sc;
            __nv_bfloat162 h01 = __floats2bfloat162_rn(f0, f1);
            __nv_bfloat162 h23 = __floats2bfloat162_rn(f2, f3);
            __nv_bfloat162 l01 = __floats2bfloat162_rn(
                f0 - __bfloat162float(h01.x), f1 - __bfloat162float(h01.y));
            __nv_bfloat162 l23 = __floats2bfloat162_rn(
                f2 - __bfloat162float(h23.x), f3 - __bfloat162float(h23.y));
            const uint32_t off = sw128((uint32_t)(arow * 128 + aseg * 64 + i * 8));
            *reinterpret_cast<__nv_bfloat162*>(smem + OFF_AHI + off)     = h01;
            *reinterpret_cast<__nv_bfloat162*>(smem + OFF_AHI + off + 4) = h23;
            *reinterpret_cast<__nv_bfloat162*>(smem + OFF_ALO + off)     = l01;
            *reinterpret_cast<__nv_bfloat162*>(smem + OFF_ALO + off + 4) = l23;
        }
        // ---- store B (straight copy), SW128 ----
        #pragma unroll
        for (int u = 0; u < 8; u++) {
            const uint32_t off = sw128((uint32_t)(bn * 128 + u * 16));
            *reinterpret_cast<uint4*>(smem + boff + off) = vb[u];
        }
        __syncthreads();

        // ---- compute: 4 k-steps of 16 ----
        #pragma unroll
        for (int kk = 0; kk < 4; kk++) {
            const uint32_t kb = (uint32_t)(kk * 32 + klane);

            // A fragments (hi and lo), 2 m-groups each
            uint32_t ahi[2][4], alo[2][4];
            #pragma unroll
            for (int g = 0; g < 2; g++) {
                const uint32_t ro = (uint32_t)((mbase + g * 16 + rlane) * 128) + kb;
                ldsm_x4(sb + OFF_AHI + sw128(ro),
                        ahi[g][0], ahi[g][1], ahi[g][2], ahi[g][3]);
                ldsm_x4(sb + OFF_ALO + sw128(ro),
                        alo[g][0], alo[g][1], alo[g][2], alo[g][3]);
            }
            // B hi fragments: 4 x4-loads cover 8 n-tiles
            uint32_t b[4][4];
            #pragma unroll
            for (int nt = 0; nt < 4; nt++) {
                const uint32_t ro = (uint32_t)((nbase + nt * 16 + rlane) * 128) + kb;
                ldsm_x4(sb + OFF_BHI + sw128(ro),
                        b[nt][0], b[nt][1], b[nt][2], b[nt][3]);
            }
            // hi*hi and lo*hi
            #pragma unroll
            for (int g = 0; g < 2; g++)
                #pragma unroll
                for (int nt = 0; nt < 4; nt++) {
                    mma16816(acc[g][nt * 2 + 0], ahi[g], b[nt][0], b[nt][2]);
                    mma16816(acc[g][nt * 2 + 1], ahi[g], b[nt][1], b[nt][3]);
                    mma16816(acc[g][nt * 2 + 0], alo[g], b[nt][0], b[nt][2]);
                    mma16816(acc[g][nt * 2 + 1], alo[g], b[nt][1], b[nt][3]);
                }
            // B lo fragments (reuse regs)
            #pragma unroll
            for (int nt = 0; nt < 4; nt++) {
                const uint32_t ro = (uint32_t)((nbase + nt * 16 + rlane) * 128) + kb;
                ldsm_x4(sb + OFF_BLO + sw128(ro),
                        b[nt][0], b[nt][1], b[nt][2], b[nt][3]);
            }
            // hi*lo
            #pragma unroll
            for (int g = 0; g < 2; g++)
                #pragma unroll
                for (int nt = 0; nt < 4; nt++) {
                    mma16816(acc[g][nt * 2 + 0], ahi[g], b[nt][0], b[nt][2]);
                    mma16816(acc[g][nt * 2 + 1], ahi[g], b[nt][1], b[nt][3]);
                }
        }
    }

    // ---- epilogue: C fragment -> global ----
    const int gq = lane >> 2;       // 0..7
    const int tq = lane & 3;        // 0..3
    #pragma unroll
    for (int g = 0; g < 2; g++) {
        const int row_lo = m0 + mbase + g * 16 + gq;
        const int row_hi = row_lo + 8;
        #pragma unroll
        for (int nt = 0; nt < 8; nt++) {
            const int col = nbase + nt * 8 + tq * 2;
            if (row_lo < N_NODES) {
                float2* p = reinterpret_cast<float2*>(
                    out + (size_t)row_lo * OUT_DIM + col);
                *p = make_float2(acc[g][nt][0], acc[g][nt][1]);
            }
            if (row_hi < N_NODES) {
                float2* p = reinterpret_cast<float2*>(
                    out + (size_t)row_hi * OUT_DIM + col);
                *p = make_float2(acc[g][nt][2], acc[g][nt][3]);
            }
        }
    }
}

// ---------------------------------------------------------------------------
// Launch
// ---------------------------------------------------------------------------
extern "C" void kernel_launch(void* const* d_in, const int* in_sizes, int n_in,
                              void* d_out, int out_size) {
    const float* x      = (const float*)d_in[0];
    const float* weight = (const float*)d_in[1];
    const float* selfw  = (const float*)d_in[2];
    const int*   ei     = (const int*)d_in[3];
    const int*   et     = (const int*)d_in[4];
    float*       out    = (float*)d_out;

    cudaFuncSetAttribute(gemm_kernel,
                         cudaFuncAttributeMaxDynamicSharedMemorySize, SMEM_TOTAL);

    zero_kernel<<<2048, 256>>>();
    convert_w_kernel<<<(OUT_DIM * K_DIM + 255) / 256, 256>>>(weight, selfw);

    const int warps   = 2 * E_EDGES;
    const int threads = 256;
    const int blocks  = (warps * 32 + threads - 1) / threads;
    scatter_kernel<<<blocks, threads>>>(x, ei, et);

    gemm_kernel<<<(N_NODES + 127) / 128, 256, SMEM_TOTAL>>>(x, out);
}

// round 4
// speedup vs baseline: 1.4067x; 1.1621x over previous
#include <cuda_runtime.h>
#include <cuda_bf16.h>
#include <cstdint>

// Problem constants
constexpr int N_NODES = 50000;
constexpr int E_EDGES = 800000;
constexpr int IN_DIM  = 128;
constexpr int OUT_DIM = 128;
constexpr int R_REL   = 8;
constexpr int K_DIM   = IN_DIM * (R_REL + 1);   // 1152
constexpr int KC      = 64;                      // K per chunk
constexpr int NCHUNK  = K_DIM / KC;              // 18

// Scratch (__device__ globals; no allocation allowed)
__device__ float g_agg[(size_t)R_REL * N_NODES * IN_DIM];   // 204.8 MB
__device__ float g_deg[(size_t)R_REL * N_NODES];            // 1.6 MB
__device__ __nv_bfloat16 g_bt_hi[(size_t)OUT_DIM * K_DIM];  // W^T hi  [128,1152]
__device__ __nv_bfloat16 g_bt_lo[(size_t)OUT_DIM * K_DIM];  // W^T lo

// ---------------------------------------------------------------------------
// Kernel 1: zero scratch
// ---------------------------------------------------------------------------
__global__ void zero_kernel() {
    const size_t total4 = ((size_t)R_REL * N_NODES * IN_DIM) / 4;
    const size_t i      = (size_t)blockIdx.x * blockDim.x + threadIdx.x;
    const size_t stride = (size_t)gridDim.x * blockDim.x;
    float4* agg4 = reinterpret_cast<float4*>(g_agg);
    const float4 z = make_float4(0.f, 0.f, 0.f, 0.f);
    for (size_t j = i; j < total4; j += stride) agg4[j] = z;
    for (size_t j = i; j < (size_t)R_REL * N_NODES; j += stride) g_deg[j] = 0.f;
}

// ---------------------------------------------------------------------------
// Kernel 2: W^T split into bf16 hi/lo.  BT[n][k] = Wcat[k][n]
// ---------------------------------------------------------------------------
__global__ void convert_w_kernel(const float* __restrict__ weight,
                                 const float* __restrict__ selfw) {
    const int idx = blockIdx.x * blockDim.x + threadIdx.x;
    if (idx >= OUT_DIM * K_DIM) return;
    const int n = idx / K_DIM;
    const int k = idx % K_DIM;
    const float v = (k < IN_DIM)
        ? selfw[(size_t)k * OUT_DIM + n]
        : weight[(size_t)(k - IN_DIM) * OUT_DIM + n];
    const __nv_bfloat16 hi = __float2bfloat16(v);
    const __nv_bfloat16 lo = __float2bfloat16(v - __bfloat162float(hi));
    g_bt_hi[idx] = hi;
    g_bt_lo[idx] = lo;
}

// ---------------------------------------------------------------------------
// Kernel 3: scatter raw features into agg[et, dst], both directions.
// ---------------------------------------------------------------------------
__global__ void scatter_kernel(const float* __restrict__ x,
                               const int*   __restrict__ ei,
                               const int*   __restrict__ et) {
    const unsigned gtid = blockIdx.x * (unsigned)blockDim.x + threadIdx.x;
    const int w    = (int)(gtid >> 5);
    const int lane = threadIdx.x & 31;
    if (w >= 2 * E_EDGES) return;

    int e, src, dst;
    if (w < E_EDGES) {
        e = w;  src = ei[e];            dst = ei[E_EDGES + e];
    } else {
        e = w - E_EDGES;  src = ei[E_EDGES + e];  dst = ei[e];
    }
    const int r = et[e];

    const float4 v = *reinterpret_cast<const float4*>(
        x + (size_t)src * IN_DIM + lane * 4);

    float* p = g_agg + ((size_t)r * N_NODES + dst) * IN_DIM + lane * 4;
    asm volatile("red.global.add.v4.f32 [%0], {%1, %2, %3, %4};"
                 :: "l"(p), "f"(v.x), "f"(v.y), "f"(v.z), "f"(v.w)
                 : "memory");

    if (lane == 0) atomicAdd(g_deg + (size_t)r * N_NODES + dst, 1.0f);
}

// ---------------------------------------------------------------------------
// mma.sync / cp.async helpers (family-common, compile under compute_103)
// ---------------------------------------------------------------------------
__device__ __forceinline__ uint32_t smem_u32(const void* p) {
    uint32_t a;
    asm("{ .reg .u64 t; cvta.to.shared.u64 t, %1; cvt.u32.u64 %0, t; }"
        : "=r"(a) : "l"(p));
    return a;
}
__device__ __forceinline__ uint64_t gmem_u64(const void* p) {
    uint64_t a;
    asm("cvta.to.global.u64 %0, %1;" : "=l"(a) : "l"(p));
    return a;
}
__device__ __forceinline__ uint32_t sw128(uint32_t o) {
    return o ^ ((o >> 3) & 0x70);
}
__device__ __forceinline__ void cp16(uint32_t dst, uint64_t src) {
    asm volatile("cp.async.cg.shared.global [%0], [%1], 16;"
                 :: "r"(dst), "l"(src) : "memory");
}
__device__ __forceinline__ void cp_commit() {
    asm volatile("cp.async.commit_group;" ::: "memory");
}
__device__ __forceinline__ void cp_wait_all() {
    asm volatile("cp.async.wait_group 0;" ::: "memory");
}
__device__ __forceinline__ void ldsm_x4(uint32_t addr,
                                        uint32_t& r0, uint32_t& r1,
                                        uint32_t& r2, uint32_t& r3) {
    asm volatile("ldmatrix.sync.aligned.m8n8.x4.shared.b16 {%0,%1,%2,%3}, [%4];"
                 : "=r"(r0), "=r"(r1), "=r"(r2), "=r"(r3) : "r"(addr));
}
__device__ __forceinline__ void mma16816(float* c, const uint32_t* a,
                                         uint32_t b0, uint32_t b1) {
    asm volatile(
        "mma.sync.aligned.m16n8k16.row.col.f32.bf16.bf16.f32 "
        "{%0,%1,%2,%3}, {%4,%5,%6,%7}, {%8,%9}, {%0,%1,%2,%3};"
        : "+f"(c[0]), "+f"(c[1]), "+f"(c[2]), "+f"(c[3])
        : "r"(a[0]), "r"(a[1]), "r"(a[2]), "r"(a[3]), "r"(b0), "r"(b1));
}

// Dynamic smem: two stages of {AHI, ALO, BHI, BLO}, each tile 16 KB SW128.
constexpr int OFF_AHI = 0;
constexpr int OFF_ALO = 16384;
constexpr int OFF_BHI = 32768;
constexpr int OFF_BLO = 49152;
constexpr int STAGE   = 65536;
constexpr int SMEM_TOTAL = 2 * STAGE;   // 128 KB

// ---------------------------------------------------------------------------
// Kernel 4: out = H @ Wcat  (bf16 3-split, double-buffered + cp.async B +
// register-prefetched A).  CTA 128x128, 8 warps (4x2), warp 32x64.
// ---------------------------------------------------------------------------
__global__ __launch_bounds__(256)
void gemm_kernel(const float* __restrict__ x, float* __restrict__ out) {
    extern __shared__ char smem[];
    const uint32_t sb = smem_u32(smem);
    const int tid  = threadIdx.x;
    const int wid  = tid >> 5;
    const int lane = tid & 31;
    const int m0   = blockIdx.x * 128;

    const int wm = wid & 3;
    const int wn = wid >> 2;
    const int mbase = wm * 32;
    const int nbase = wn * 64;
    const int rlane = lane & 15;
    const int klane = (lane >> 4) * 16;

    // A-load mapping: 2 threads per row, 32 floats each
    const int  arow = tid >> 1;
    const int  aseg = tid & 1;
    const int  mg   = m0 + arow;
    const bool av   = (mg < N_NODES);

    // B cp.async mapping: threads 0-127 -> hi, 128-255 -> lo; row = tid&127
    const int bn   = tid & 127;
    const uint64_t bgsrc = gmem_u64(
        ((tid >> 7) ? g_bt_lo : g_bt_hi) + (size_t)bn * K_DIM);
    const int btile = (tid >> 7) ? OFF_BLO : OFF_BHI;

    // ---- helpers as macros over locals ----
    float4 va[8];
    float  sc = 0.f;

    auto load_a = [&](int ch) {
        if (!av) { return; }
        const float* ap;
        if (ch < 2) {
            ap = x + (size_t)mg * IN_DIM + ch * 64;
            sc = 1.0f;
        } else {
            const int r  = (ch - 2) >> 1;
            const int ko = ((ch - 2) & 1) * 64;
            ap = g_agg + ((size_t)r * N_NODES + mg) * IN_DIM + ko;
            const float d = g_deg[(size_t)r * N_NODES + mg];
            sc = (d > 0.f) ? (1.0f / d) : 0.0f;
        }
        #pragma unroll
        for (int i = 0; i < 8; i++)
            va[i] = *reinterpret_cast<const float4*>(ap + aseg * 32 + i * 4);
    };
    auto store_a = [&](int stage_off) {
        #pragma unroll
        for (int i = 0; i < 8; i++) {
            float f0 = va[i].x * sc, f1 = va[i].y * sc,
                  f2 = va[i].z * sc, f3 = va[i].w * sc;
            if (!av) { f0 = f1 = f2 = f3 = 0.f; }
            __nv_bfloat162 h01 = __floats2bfloat162_rn(f0, f1);
            __nv_bfloat162 h23 = __floats2bfloat162_rn(f2, f3);
            __nv_bfloat162 l01 = __floats2bfloat162_rn(
                f0 - __bfloat162float(h01.x), f1 - __bfloat162float(h01.y));
            __nv_bfloat162 l23 = __floats2bfloat162_rn(
                f2 - __bfloat162float(h23.x), f3 - __bfloat162float(h23.y));
            const uint32_t off = sw128((uint32_t)(arow * 128 + aseg * 64 + i * 8));
            char* s = smem + stage_off;
            *reinterpret_cast<__nv_bfloat162*>(s + OFF_AHI + off)     = h01;
            *reinterpret_cast<__nv_bfloat162*>(s + OFF_AHI + off + 4) = h23;
            *reinterpret_cast<__nv_bfloat162*>(s + OFF_ALO + off)     = l01;
            *reinterpret_cast<__nv_bfloat162*>(s + OFF_ALO + off + 4) = l23;
        }
    };
    auto issue_b = [&](int ch, int stage_off) {
        const uint64_t src = bgsrc + (size_t)ch * KC * 2;
        const uint32_t dst = sb + stage_off + btile;
        #pragma unroll
        for (int u = 0; u < 8; u++)
            cp16(dst + sw128((uint32_t)(bn * 128 + u * 16)), src + u * 16);
        cp_commit();
    };

    float acc[2][8][4];
    #pragma unroll
    for (int i = 0; i < 2; i++)
        #pragma unroll
        for (int j = 0; j < 8; j++)
            #pragma unroll
            for (int q = 0; q < 4; q++) acc[i][j][q] = 0.f;

    // ---- prologue: fill stage 0 with chunk 0, prefetch A(1) ----
    issue_b(0, 0);
    load_a(0);
    store_a(0);
    float sc_saved;
    load_a(1);          // in-flight during wait
    sc_saved = sc;
    cp_wait_all();
    __syncthreads();

    int buf = 0;
    for (int ch = 0; ch < NCHUNK; ch++) {
        const int cur  = buf * STAGE;
        const int nxt  = (buf ^ 1) * STAGE;

        if (ch + 1 < NCHUNK) {
            issue_b(ch + 1, nxt);     // async B for next chunk
            sc = sc_saved;
            store_a(nxt);             // convert prefetched A(ch+1)
        }
        if (ch + 2 < NCHUNK) {
            load_a(ch + 2);           // issue LDGs; land during compute
            sc_saved = sc;
        }

        // ---- compute chunk ch from stage cur ----
        const uint32_t sA_hi = sb + cur + OFF_AHI;
        const uint32_t sA_lo = sb + cur + OFF_ALO;
        const uint32_t sB_hi = sb + cur + OFF_BHI;
        const uint32_t sB_lo = sb + cur + OFF_BLO;
        #pragma unroll
        for (int kk = 0; kk < 4; kk++) {
            const uint32_t kb = (uint32_t)(kk * 32 + klane);
            uint32_t ahi[2][4], alo[2][4];
            #pragma unroll
            for (int g = 0; g < 2; g++) {
                const uint32_t ro = (uint32_t)((mbase + g * 16 + rlane) * 128) + kb;
                ldsm_x4(sA_hi + sw128(ro), ahi[g][0], ahi[g][1], ahi[g][2], ahi[g][3]);
                ldsm_x4(sA_lo + sw128(ro), alo[g][0], alo[g][1], alo[g][2], alo[g][3]);
            }
            uint32_t b[4][4];
            #pragma unroll
            for (int nt = 0; nt < 4; nt++) {
                const uint32_t ro = (uint32_t)((nbase + nt * 16 + rlane) * 128) + kb;
                ldsm_x4(sB_hi + sw128(ro), b[nt][0], b[nt][1], b[nt][2], b[nt][3]);
            }
            #pragma unroll
            for (int g = 0; g < 2; g++)
                #pragma unroll
                for (int nt = 0; nt < 4; nt++) {
                    mma16816(acc[g][nt * 2 + 0], ahi[g], b[nt][0], b[nt][2]);
                    mma16816(acc[g][nt * 2 + 1], ahi[g], b[nt][1], b[nt][3]);
                    mma16816(acc[g][nt * 2 + 0], alo[g], b[nt][0], b[nt][2]);
                    mma16816(acc[g][nt * 2 + 1], alo[g], b[nt][1], b[nt][3]);
                }
            #pragma unroll
            for (int nt = 0; nt < 4; nt++) {
                const uint32_t ro = (uint32_t)((nbase + nt * 16 + rlane) * 128) + kb;
                ldsm_x4(sB_lo + sw128(ro), b[nt][0], b[nt][1], b[nt][2], b[nt][3]);
            }
            #pragma unroll
            for (int g = 0; g < 2; g++)
                #pragma unroll
                for (int nt = 0; nt < 4; nt++) {
                    mma16816(acc[g][nt * 2 + 0], ahi[g], b[nt][0], b[nt][2]);
                    mma16816(acc[g][nt * 2 + 1], ahi[g], b[nt][1], b[nt][3]);
                }
        }

        cp_wait_all();      // B(ch+1) must be resident before next iter reads
        __syncthreads();    // all MMA reads of 'cur' + A stores of 'nxt' done
        buf ^= 1;
    }

    // ---- epilogue ----
    const int gq = lane >> 2;
    const int tq = lane & 3;
    #pragma unroll
    for (int g = 0; g < 2; g++) {
        const int row_lo = m0 + mbase + g * 16 + gq;
        const int row_hi = row_lo + 8;
        #pragma unroll
        for (int nt = 0; nt < 8; nt++) {
            const int col = nbase + nt * 8 + tq * 2;
            if (row_lo < N_NODES) {
                *reinterpret_cast<float2*>(out + (size_t)row_lo * OUT_DIM + col) =
                    make_float2(acc[g][nt][0], acc[g][nt][1]);
            }
            if (row_hi < N_NODES) {
                *reinterpret_cast<float2*>(out + (size_t)row_hi * OUT_DIM + col) =
                    make_float2(acc[g][nt][2], acc[g][nt][3]);
            }
        }
    }
}

// ---------------------------------------------------------------------------
// Launch
// ---------------------------------------------------------------------------
extern "C" void kernel_launch(void* const* d_in, const int* in_sizes, int n_in,
                              void* d_out, int out_size) {
    const float* x      = (const float*)d_in[0];
    const float* weight = (const float*)d_in[1];
    const float* selfw  = (const float*)d_in[2];
    const int*   ei     = (const int*)d_in[3];
    const int*   et     = (const int*)d_in[4];
    float*       out    = (float*)d_out;

    cudaFuncSetAttribute(gemm_kernel,
                         cudaFuncAttributeMaxDynamicSharedMemorySize, SMEM_TOTAL);

    zero_kernel<<<2048, 256>>>();
    convert_w_kernel<<<(OUT_DIM * K_DIM + 255) / 256, 256>>>(weight, selfw);

    const int warps   = 2 * E_EDGES;
    const int threads = 256;
    const int blocks  = (warps * 32 + threads - 1) / threads;
    scatter_kernel<<<blocks, threads>>>(x, ei, et);

    gemm_kernel<<<(N_NODES + 127) / 128, 256, SMEM_TOTAL>>>(x, out);
}

// round 5
// speedup vs baseline: 1.4269x; 1.0143x over previous
#include <cuda_runtime.h>
#include <cuda_bf16.h>
#include <cstdint>

// Problem constants
constexpr int N_NODES = 50000;
constexpr int E_EDGES = 800000;
constexpr int IN_DIM  = 128;
constexpr int OUT_DIM = 128;
constexpr int R_REL   = 8;
constexpr int K_DIM   = IN_DIM * (R_REL + 1);   // 1152
constexpr int KC      = 64;                      // K per chunk
constexpr int NCHUNK  = K_DIM / KC;              // 18
constexpr int MAXDEG  = 64;                      // Poisson(4) max ~25; ample

// Scratch (__device__ globals; no allocation allowed)
__device__ uint32_t g_cnt[R_REL * N_NODES];                       // 1.6 MB
__device__ uint32_t g_idx[(size_t)R_REL * N_NODES * MAXDEG];      // 102.4 MB
__device__ __nv_bfloat16 g_bt_hi[(size_t)OUT_DIM * K_DIM];        // W^T hi
__device__ __nv_bfloat16 g_bt_lo[(size_t)OUT_DIM * K_DIM];        // W^T lo

// ---------------------------------------------------------------------------
// Kernel 1: zero the per-segment counters
// ---------------------------------------------------------------------------
__global__ void zero_cnt_kernel() {
    const int i = blockIdx.x * blockDim.x + threadIdx.x;
    if (i < R_REL * N_NODES) g_cnt[i] = 0u;
}

// ---------------------------------------------------------------------------
// Kernel 2: W^T split into bf16 hi/lo.  BT[n][k] = Wcat[k][n]
// ---------------------------------------------------------------------------
__global__ void convert_w_kernel(const float* __restrict__ weight,
                                 const float* __restrict__ selfw) {
    const int idx = blockIdx.x * blockDim.x + threadIdx.x;
    if (idx >= OUT_DIM * K_DIM) return;
    const int n = idx / K_DIM;
    const int k = idx % K_DIM;
    const float v = (k < IN_DIM)
        ? selfw[(size_t)k * OUT_DIM + n]
        : weight[(size_t)(k - IN_DIM) * OUT_DIM + n];
    const __nv_bfloat16 hi = __float2bfloat16(v);
    const __nv_bfloat16 lo = __float2bfloat16(v - __bfloat162float(hi));
    g_bt_hi[idx] = hi;
    g_bt_lo[idx] = lo;
}

// ---------------------------------------------------------------------------
// Kernel 3: build CSR-ish buckets. One thread per undirected edge; emits
// both directed messages: (r,dst)<-src and (r,src)<-dst.
// ---------------------------------------------------------------------------
__global__ void fill_kernel(const int* __restrict__ ei,
                            const int* __restrict__ et) {
    const int e = blockIdx.x * blockDim.x + threadIdx.x;
    if (e >= E_EDGES) return;
    const int src = ei[e];
    const int dst = ei[E_EDGES + e];
    const int r   = et[e];

    const int seg1 = r * N_NODES + dst;
    uint32_t p1 = atomicAdd(&g_cnt[seg1], 1u);
    if (p1 < MAXDEG) g_idx[(size_t)seg1 * MAXDEG + p1] = (uint32_t)src;

    const int seg2 = r * N_NODES + src;
    uint32_t p2 = atomicAdd(&g_cnt[seg2], 1u);
    if (p2 < MAXDEG) g_idx[(size_t)seg2 * MAXDEG + p2] = (uint32_t)dst;
}

// ---------------------------------------------------------------------------
// mma.sync / cp.async helpers (family-common, compile under compute_103)
// ---------------------------------------------------------------------------
__device__ __forceinline__ uint32_t smem_u32(const void* p) {
    uint32_t a;
    asm("{ .reg .u64 t; cvta.to.shared.u64 t, %1; cvt.u32.u64 %0, t; }"
        : "=r"(a) : "l"(p));
    return a;
}
__device__ __forceinline__ uint64_t gmem_u64(const void* p) {
    uint64_t a;
    asm("cvta.to.global.u64 %0, %1;" : "=l"(a) : "l"(p));
    return a;
}
__device__ __forceinline__ uint32_t sw128(uint32_t o) {
    return o ^ ((o >> 3) & 0x70);
}
__device__ __forceinline__ void cp16(uint32_t dst, uint64_t src) {
    asm volatile("cp.async.cg.shared.global [%0], [%1], 16;"
                 :: "r"(dst), "l"(src) : "memory");
}
__device__ __forceinline__ void cp_commit() {
    asm volatile("cp.async.commit_group;" ::: "memory");
}
__device__ __forceinline__ void cp_wait_all() {
    asm volatile("cp.async.wait_group 0;" ::: "memory");
}
__device__ __forceinline__ void ldsm_x4(uint32_t addr,
                                        uint32_t& r0, uint32_t& r1,
                                        uint32_t& r2, uint32_t& r3) {
    asm volatile("ldmatrix.sync.aligned.m8n8.x4.shared.b16 {%0,%1,%2,%3}, [%4];"
                 : "=r"(r0), "=r"(r1), "=r"(r2), "=r"(r3) : "r"(addr));
}
__device__ __forceinline__ void mma16816(float* c, const uint32_t* a,
                                         uint32_t b0, uint32_t b1) {
    asm volatile(
        "mma.sync.aligned.m16n8k16.row.col.f32.bf16.bf16.f32 "
        "{%0,%1,%2,%3}, {%4,%5,%6,%7}, {%8,%9}, {%0,%1,%2,%3};"
        : "+f"(c[0]), "+f"(c[1]), "+f"(c[2]), "+f"(c[3])
        : "r"(a[0]), "r"(a[1]), "r"(a[2]), "r"(a[3]), "r"(b0), "r"(b1));
}

// Dynamic smem: two stages of {AHI, ALO, BHI, BLO}, each tile 16 KB SW128.
constexpr int OFF_AHI = 0;
constexpr int OFF_ALO = 16384;
constexpr int OFF_BHI = 32768;
constexpr int OFF_BLO = 49152;
constexpr int STAGE   = 65536;
constexpr int SMEM_TOTAL = 2 * STAGE;   // 128 KB

// ---------------------------------------------------------------------------
// Kernel 4: out = H @ Wcat with FUSED neighbor gather.
//   H[v,k] = k<128 ? x[v,k] : (1/deg(r,v)) * sum_{u in N_r(v)} x[u, k&127]
// bf16 3-split (hi*hi + hi*lo + lo*hi) via mma.sync.m16n8k16.
// CTA 128x128, 8 warps (4x2), warp 32x64; double-buffered smem.
// ---------------------------------------------------------------------------
__global__ __launch_bounds__(256)
void gemm_kernel(const float* __restrict__ x, float* __restrict__ out) {
    extern __shared__ char smem[];
    const uint32_t sb = smem_u32(smem);
    const int tid  = threadIdx.x;
    const int wid  = tid >> 5;
    const int lane = tid & 31;
    const int m0   = blockIdx.x * 128;

    const int wm = wid & 3;
    const int wn = wid >> 2;
    const int mbase = wm * 32;
    const int nbase = wn * 64;
    const int rlane = lane & 15;
    const int klane = (lane >> 4) * 16;

    // A mapping: 2 threads per row, 32 floats (8 float4) each
    const int  arow = tid >> 1;
    const int  aseg = tid & 1;
    const int  mg   = m0 + arow;
    const bool av   = (mg < N_NODES);

    // B cp.async mapping: threads 0-127 -> hi, 128-255 -> lo; row = tid&127
    const int bn   = tid & 127;
    const uint64_t bgsrc = gmem_u64(
        ((tid >> 7) ? g_bt_lo : g_bt_hi) + (size_t)bn * K_DIM);
    const int btile = (tid >> 7) ? OFF_BLO : OFF_BHI;

    float4 va[8];
    float  sc = 0.f;

    // load_a: produce the raw A fragment for chunk ch in va[], scale in sc.
    auto load_a = [&](int ch) {
        #pragma unroll
        for (int i = 0; i < 8; i++) va[i] = make_float4(0.f, 0.f, 0.f, 0.f);
        sc = 0.f;
        if (!av) return;
        if (ch < 2) {
            const float4* xp = reinterpret_cast<const float4*>(
                x + (size_t)mg * IN_DIM + ch * 64 + aseg * 32);
            #pragma unroll
            for (int i = 0; i < 8; i++) va[i] = xp[i];
            sc = 1.0f;
        } else {
            const int r  = (ch - 2) >> 1;
            const int ko = ((ch - 2) & 1) * 64;
            const int seg = r * N_NODES + mg;
            const uint32_t cnt = g_cnt[seg];
            const int d = (cnt < MAXDEG) ? (int)cnt : MAXDEG;
            const uint32_t* __restrict__ lst = g_idx + (size_t)seg * MAXDEG;
            for (int j = 0; j < d; j++) {
                const float4* xp = reinterpret_cast<const float4*>(
                    x + (size_t)lst[j] * IN_DIM + ko + aseg * 32);
                #pragma unroll
                for (int i = 0; i < 8; i++) {
                    const float4 t = xp[i];
                    va[i].x += t.x; va[i].y += t.y;
                    va[i].z += t.z; va[i].w += t.w;
                }
            }
            sc = (cnt > 0u) ? (1.0f / (float)cnt) : 0.0f;
        }
    };
    auto store_a = [&](int stage_off) {
        #pragma unroll
        for (int i = 0; i < 8; i++) {
            const float f0 = va[i].x * sc, f1 = va[i].y * sc,
                        f2 = va[i].z * sc, f3 = va[i].w * sc;
            __nv_bfloat162 h01 = __floats2bfloat162_rn(f0, f1);
            __nv_bfloat162 h23 = __floats2bfloat162_rn(f2, f3);
            __nv_bfloat162 l01 = __floats2bfloat162_rn(
                f0 - __bfloat162float(h01.x), f1 - __bfloat162float(h01.y));
            __nv_bfloat162 l23 = __floats2bfloat162_rn(
                f2 - __bfloat162float(h23.x), f3 - __bfloat162float(h23.y));
            const uint32_t off = sw128((uint32_t)(arow * 128 + aseg * 64 + i * 8));
            char* s = smem + stage_off;
            *reinterpret_cast<__nv_bfloat162*>(s + OFF_AHI + off)     = h01;
            *reinterpret_cast<__nv_bfloat162*>(s + OFF_AHI + off + 4) = h23;
            *reinterpret_cast<__nv_bfloat162*>(s + OFF_ALO + off)     = l01;
            *reinterpret_cast<__nv_bfloat162*>(s + OFF_ALO + off + 4) = l23;
        }
    };
    auto issue_b = [&](int ch, int stage_off) {
        const uint64_t src = bgsrc + (size_t)ch * KC * 2;
        const uint32_t dst = sb + stage_off + btile;
        #pragma unroll
        for (int u = 0; u < 8; u++)
            cp16(dst + sw128((uint32_t)(bn * 128 + u * 16)), src + u * 16);
        cp_commit();
    };

    float acc[2][8][4];
    #pragma unroll
    for (int i = 0; i < 2; i++)
        #pragma unroll
        for (int j = 0; j < 8; j++)
            #pragma unroll
            for (int q = 0; q < 4; q++) acc[i][j][q] = 0.f;

    // ---- prologue: stage 0 = chunk 0; prefetch A(1) ----
    issue_b(0, 0);
    load_a(0);
    store_a(0);
    load_a(1);
    float sc_saved = sc;
    cp_wait_all();
    __syncthreads();

    int buf = 0;
    for (int ch = 0; ch < NCHUNK; ch++) {
        const int cur = buf * STAGE;
        const int nxt = (buf ^ 1) * STAGE;

        if (ch + 1 < NCHUNK) {
            issue_b(ch + 1, nxt);
            sc = sc_saved;
            store_a(nxt);             // convert prefetched A(ch+1)
        }
        if (ch + 2 < NCHUNK) {
            load_a(ch + 2);           // gather lands during compute
            sc_saved = sc;
        }

        const uint32_t sA_hi = sb + cur + OFF_AHI;
        const uint32_t sA_lo = sb + cur + OFF_ALO;
        const uint32_t sB_hi = sb + cur + OFF_BHI;
        const uint32_t sB_lo = sb + cur + OFF_BLO;
        #pragma unroll
        for (int kk = 0; kk < 4; kk++) {
            const uint32_t kb = (uint32_t)(kk * 32 + klane);
            uint32_t ahi[2][4], alo[2][4];
            #pragma unroll
            for (int g = 0; g < 2; g++) {
                const uint32_t ro = (uint32_t)((mbase + g * 16 + rlane) * 128) + kb;
                ldsm_x4(sA_hi + sw128(ro), ahi[g][0], ahi[g][1], ahi[g][2], ahi[g][3]);
                ldsm_x4(sA_lo + sw128(ro), alo[g][0], alo[g][1], alo[g][2], alo[g][3]);
            }
            uint32_t b[4][4];
            #pragma unroll
            for (int nt = 0; nt < 4; nt++) {
                const uint32_t ro = (uint32_t)((nbase + nt * 16 + rlane) * 128) + kb;
                ldsm_x4(sB_hi + sw128(ro), b[nt][0], b[nt][1], b[nt][2], b[nt][3]);
            }
            #pragma unroll
            for (int g = 0; g < 2; g++)
                #pragma unroll
                for (int nt = 0; nt < 4; nt++) {
                    mma16816(acc[g][nt * 2 + 0], ahi[g], b[nt][0], b[nt][2]);
                    mma16816(acc[g][nt * 2 + 1], ahi[g], b[nt][1], b[nt][3]);
                    mma16816(acc[g][nt * 2 + 0], alo[g], b[nt][0], b[nt][2]);
                    mma16816(acc[g][nt * 2 + 1], alo[g], b[nt][1], b[nt][3]);
                }
            #pragma unroll
            for (int nt = 0; nt < 4; nt++) {
                const uint32_t ro = (uint32_t)((nbase + nt * 16 + rlane) * 128) + kb;
                ldsm_x4(sB_lo + sw128(ro), b[nt][0], b[nt][1], b[nt][2], b[nt][3]);
            }
            #pragma unroll
            for (int g = 0; g < 2; g++)
                #pragma unroll
                for (int nt = 0; nt < 4; nt++) {
                    mma16816(acc[g][nt * 2 + 0], ahi[g], b[nt][0], b[nt][2]);
                    mma16816(acc[g][nt * 2 + 1], ahi[g], b[nt][1], b[nt][3]);
                }
        }

        cp_wait_all();
        __syncthreads();
        buf ^= 1;
    }

    // ---- epilogue ----
    const int gq = lane >> 2;
    const int tq = lane & 3;
    #pragma unroll
    for (int g = 0; g < 2; g++) {
        const int row_lo = m0 + mbase + g * 16 + gq;
        const int row_hi = row_lo + 8;
        #pragma unroll
        for (int nt = 0; nt < 8; nt++) {
            const int col = nbase + nt * 8 + tq * 2;
            if (row_lo < N_NODES) {
                *reinterpret_cast<float2*>(out + (size_t)row_lo * OUT_DIM + col) =
                    make_float2(acc[g][nt][0], acc[g][nt][1]);
            }
            if (row_hi < N_NODES) {
                *reinterpret_cast<float2*>(out + (size_t)row_hi * OUT_DIM + col) =
                    make_float2(acc[g][nt][2], acc[g][nt][3]);
            }
        }
    }
}

// ---------------------------------------------------------------------------
// Launch
// ---------------------------------------------------------------------------
extern "C" void kernel_launch(void* const* d_in, const int* in_sizes, int n_in,
                              void* d_out, int out_size) {
    const float* x      = (const float*)d_in[0];
    const float* weight = (const float*)d_in[1];
    const float* selfw  = (const float*)d_in[2];
    const int*   ei     = (const int*)d_in[3];
    const int*   et     = (const int*)d_in[4];
    float*       out    = (float*)d_out;

    cudaFuncSetAttribute(gemm_kernel,
                         cudaFuncAttributeMaxDynamicSharedMemorySize, SMEM_TOTAL);

    zero_cnt_kernel<<<(R_REL * N_NODES + 255) / 256, 256>>>();
    convert_w_kernel<<<(OUT_DIM * K_DIM + 255) / 256, 256>>>(weight, selfw);
    fill_kernel<<<(E_EDGES + 255) / 256, 256>>>(ei, et);
    gemm_kernel<<<(N_NODES + 127) / 128, 256, SMEM_TOTAL>>>(x, out);
}

// round 7
// speedup vs baseline: 2.2197x; 1.5556x over previous
#include <cuda_runtime.h>
#include <cuda_bf16.h>
#include <cstdint>

// Problem constants
constexpr int N_NODES = 50000;
constexpr int E_EDGES = 800000;
constexpr int IN_DIM  = 128;
constexpr int OUT_DIM = 128;
constexpr int R_REL   = 8;
constexpr int K_DIM   = IN_DIM * (R_REL + 1);   // 1152
constexpr int KC      = 32;                      // K per chunk
constexpr int NCHUNK  = K_DIM / KC;              // 36
constexpr int MAXDEG  = 64;                      // Poisson(4); ample

// H / W^T storage: per (row, chunk) one 128B block = [hi 32 bf16 | lo 32 bf16]
__device__ uint32_t g_cnt[R_REL * N_NODES];                      // 1.6 MB
__device__ uint32_t g_idx[(size_t)R_REL * N_NODES * MAXDEG];     // 102.4 MB
__device__ __nv_bfloat16 g_h [(size_t)N_NODES * K_DIM * 2];      // 230 MB
__device__ __nv_bfloat16 g_bt[(size_t)OUT_DIM * K_DIM * 2];      // 0.6 MB

// ---------------------------------------------------------------------------
// Kernel 1: zero per-segment counters
// ---------------------------------------------------------------------------
__global__ void zero_cnt_kernel() {
    const int i = blockIdx.x * blockDim.x + threadIdx.x;
    if (i < R_REL * N_NODES) g_cnt[i] = 0u;
}

// ---------------------------------------------------------------------------
// Kernel 2: W^T -> blocked bf16 hi/lo.  BT[n][k] = Wcat[k][n]
// ---------------------------------------------------------------------------
__global__ void convert_w_kernel(const float* __restrict__ weight,
                                 const float* __restrict__ selfw) {
    const int idx = blockIdx.x * blockDim.x + threadIdx.x;
    if (idx >= OUT_DIM * K_DIM) return;
    const int n = idx / K_DIM;
    const int k = idx % K_DIM;
    const float v = (k < IN_DIM)
        ? selfw[(size_t)k * OUT_DIM + n]
        : weight[(size_t)(k - IN_DIM) * OUT_DIM + n];
    const __nv_bfloat16 hi = __float2bfloat16(v);
    const __nv_bfloat16 lo = __float2bfloat16(v - __bfloat162float(hi));
    const int c = k / KC, p = k % KC;
    __nv_bfloat16* blk = g_bt + ((size_t)n * NCHUNK + c) * 64;
    blk[p]      = hi;
    blk[32 + p] = lo;
}

// ---------------------------------------------------------------------------
// Kernel 3: bucket build (both directed messages per undirected edge)
// ---------------------------------------------------------------------------
__global__ void fill_kernel(const int* __restrict__ ei,
                            const int* __restrict__ et) {
    const int e = blockIdx.x * blockDim.x + threadIdx.x;
    if (e >= E_EDGES) return;
    const int src = ei[e];
    const int dst = ei[E_EDGES + e];
    const int r   = et[e];

    const int seg1 = r * N_NODES + dst;
    uint32_t p1 = atomicAdd(&g_cnt[seg1], 1u);
    if (p1 < MAXDEG) g_idx[(size_t)seg1 * MAXDEG + p1] = (uint32_t)src;

    const int seg2 = r * N_NODES + src;
    uint32_t p2 = atomicAdd(&g_cnt[seg2], 1u);
    if (p2 < MAXDEG) g_idx[(size_t)seg2 * MAXDEG + p2] = (uint32_t)dst;
}

// ---------------------------------------------------------------------------
// Kernel 4: aggregate.  One warp per (v, r9) segment, r9=0 -> x itself,
// r9=1..8 -> mean over relation-(r9-1) neighbors.  Writes H blocked bf16.
// ---------------------------------------------------------------------------
__global__ __launch_bounds__(256)
void agg_kernel(const float* __restrict__ x) {
    const int w = blockIdx.x * 8 + (threadIdx.x >> 5);
    if (w >= N_NODES * 9) return;
    const int lane = threadIdx.x & 31;
    const int v  = w / 9;
    const int r9 = w - v * 9;

    const float4* __restrict__ x4 = reinterpret_cast<const float4*>(x);
    float4 acc = make_float4(0.f, 0.f, 0.f, 0.f);
    float  sc;

    if (r9 == 0) {
        acc = x4[(size_t)v * 32 + lane];
        sc  = 1.0f;
    } else {
        const int seg = (r9 - 1) * N_NODES + v;
        const uint32_t cnt = g_cnt[seg];
        const int d = (cnt < MAXDEG) ? (int)cnt : MAXDEG;
        const uint32_t* __restrict__ lst = g_idx + (size_t)seg * MAXDEG;
        for (int j = 0; j < d; j++) {
            const float4 t = x4[(size_t)lst[j] * 32 + lane];
            acc.x += t.x; acc.y += t.y; acc.z += t.z; acc.w += t.w;
        }
        sc = (cnt > 0u) ? (1.0f / (float)cnt) : 0.0f;
    }

    const float f0 = acc.x * sc, f1 = acc.y * sc, f2 = acc.z * sc, f3 = acc.w * sc;
    const __nv_bfloat162 h01 = __floats2bfloat162_rn(f0, f1);
    const __nv_bfloat162 h23 = __floats2bfloat162_rn(f2, f3);
    const __nv_bfloat162 l01 = __floats2bfloat162_rn(
        f0 - __bfloat162float(h01.x), f1 - __bfloat162float(h01.y));
    const __nv_bfloat162 l23 = __floats2bfloat162_rn(
        f2 - __bfloat162float(h23.x), f3 - __bfloat162float(h23.y));

    const int c   = r9 * 4 + (lane >> 3);        // chunk index
    const int off = (lane & 7) * 4;              // element within chunk
    __nv_bfloat16* blk = g_h + ((size_t)v * NCHUNK + c) * 64;
    *reinterpret_cast<__nv_bfloat162*>(blk + off)          = h01;
    *reinterpret_cast<__nv_bfloat162*>(blk + off + 2)      = h23;
    *reinterpret_cast<__nv_bfloat162*>(blk + 32 + off)     = l01;
    *reinterpret_cast<__nv_bfloat162*>(blk + 32 + off + 2) = l23;
}

// ---------------------------------------------------------------------------
// mma.sync / cp.async helpers
// ---------------------------------------------------------------------------
__device__ __forceinline__ uint32_t smem_u32(const void* p) {
    uint32_t a;
    asm("{ .reg .u64 t; cvta.to.shared.u64 t, %1; cvt.u32.u64 %0, t; }"
        : "=r"(a) : "l"(p));
    return a;
}
__device__ __forceinline__ uint64_t gmem_u64(const void* p) {
    uint64_t a;
    asm("cvta.to.global.u64 %0, %1;" : "=l"(a) : "l"(p));
    return a;
}
__device__ __forceinline__ uint32_t sw128(uint32_t o) {
    return o ^ ((o >> 3) & 0x70);
}
__device__ __forceinline__ void cp16(uint32_t dst, uint64_t src) {
    asm volatile("cp.async.cg.shared.global [%0], [%1], 16;"
                 :: "r"(dst), "l"(src) : "memory");
}
__device__ __forceinline__ void cp_commit() {
    asm volatile("cp.async.commit_group;" ::: "memory");
}
template<int n> __device__ __forceinline__ void cp_wait() {
    asm volatile("cp.async.wait_group %0;" :: "n"(n) : "memory");
}
__device__ __forceinline__ void ldsm_x4(uint32_t addr,
                                        uint32_t& r0, uint32_t& r1,
                                        uint32_t& r2, uint32_t& r3) {
    asm volatile("ldmatrix.sync.aligned.m8n8.x4.shared.b16 {%0,%1,%2,%3}, [%4];"
                 : "=r"(r0), "=r"(r1), "=r"(r2), "=r"(r3) : "r"(addr));
}
__device__ __forceinline__ void mma16816(float* c, const uint32_t* a,
                                         uint32_t b0, uint32_t b1) {
    asm volatile(
        "mma.sync.aligned.m16n8k16.row.col.f32.bf16.bf16.f32 "
        "{%0,%1,%2,%3}, {%4,%5,%6,%7}, {%8,%9}, {%0,%1,%2,%3};"
        : "+f"(c[0]), "+f"(c[1]), "+f"(c[2]), "+f"(c[3])
        : "r"(a[0]), "r"(a[1]), "r"(a[2]), "r"(a[3]), "r"(b0), "r"(b1));
}

// Smem: 3 stages x {A tile 16KB, B tile 16KB}. Tile row = 128B [hi64B|lo64B].
constexpr int STAGE   = 32768;
constexpr int OFF_B   = 16384;
constexpr int SMEM_TOTAL = 3 * STAGE;   // 96 KB -> 2 CTAs/SM

// ---------------------------------------------------------------------------
// Kernel 5: out = H @ Wcat, pure bf16 3-split GEMM (hi*hi + hi*lo + lo*hi).
// CTA 128x128, 8 warps (4x2), KC=32, 3-stage cp.async ring.
// ---------------------------------------------------------------------------
__global__ __launch_bounds__(256, 2)
void gemm_kernel(float* __restrict__ out) {
    extern __shared__ char smem[];
    const uint32_t sb = smem_u32(smem);
    const int tid  = threadIdx.x;
    const int wid  = tid >> 5;
    const int lane = tid & 31;
    const int m0   = blockIdx.x * 128;

    const int wm = wid & 3, wn = wid >> 2;
    const int mbase = wm * 32, nbase = wn * 64;
    const int rlane = lane & 15;
    const int klane = (lane >> 4) * 16;

    // cp.async mapping: 2 threads/row, each one 64B half (4x cp16)
    const int crow = tid >> 1;
    const int chalf = (tid & 1) * 64;
    const int arow = (m0 + crow < N_NODES) ? (m0 + crow) : (N_NODES - 1);
    const uint64_t gA = gmem_u64(g_h)  + ((size_t)arow * NCHUNK) * 128 + chalf;
    const uint64_t gB = gmem_u64(g_bt) + ((size_t)crow * NCHUNK) * 128 + chalf;
    const uint32_t rowbase = (uint32_t)(crow * 128 + chalf);

    auto issue = [&](int ch, int s) {
        const uint32_t da = sb + s * STAGE;
        const uint32_t db = da + OFF_B;
        const uint64_t sa = gA + (size_t)ch * 128;
        const uint64_t sbsrc = gB + (size_t)ch * 128;
        // NOTE: swizzle applied PER 16-byte transfer (must match ldmatrix side)
        #pragma unroll
        for (int i = 0; i < 4; i++) cp16(da + sw128(rowbase + i * 16), sa + i * 16);
        #pragma unroll
        for (int i = 0; i < 4; i++) cp16(db + sw128(rowbase + i * 16), sbsrc + i * 16);
        cp_commit();
    };

    float acc[2][8][4];
    #pragma unroll
    for (int i = 0; i < 2; i++)
        #pragma unroll
        for (int j = 0; j < 8; j++)
            #pragma unroll
            for (int q = 0; q < 4; q++) acc[i][j][q] = 0.f;

    issue(0, 0);
    issue(1, 1);

    for (int ch = 0; ch < NCHUNK; ch++) {
        if (ch + 2 < NCHUNK) { issue(ch + 2, (ch + 2) % 3); cp_wait<2>(); }
        else if (ch + 1 < NCHUNK) { cp_wait<1>(); }
        else { cp_wait<0>(); }
        __syncthreads();

        const uint32_t sA = sb + (ch % 3) * STAGE;
        const uint32_t sB = sA + OFF_B;
        #pragma unroll
        for (int kk = 0; kk < 2; kk++) {
            const uint32_t kb = (uint32_t)(kk * 32 + klane);
            uint32_t ahi[2][4], alo[2][4];
            #pragma unroll
            for (int g = 0; g < 2; g++) {
                const uint32_t ro = (uint32_t)((mbase + g * 16 + rlane) * 128);
                ldsm_x4(sA + sw128(ro + kb),      ahi[g][0], ahi[g][1], ahi[g][2], ahi[g][3]);
                ldsm_x4(sA + sw128(ro + 64 + kb), alo[g][0], alo[g][1], alo[g][2], alo[g][3]);
            }
            uint32_t b[4][4];
            #pragma unroll
            for (int nt = 0; nt < 4; nt++) {
                const uint32_t ro = (uint32_t)((nbase + nt * 16 + rlane) * 128);
                ldsm_x4(sB + sw128(ro + kb), b[nt][0], b[nt][1], b[nt][2], b[nt][3]);
            }
            #pragma unroll
            for (int g = 0; g < 2; g++)
                #pragma unroll
                for (int nt = 0; nt < 4; nt++) {
                    mma16816(acc[g][nt * 2 + 0], ahi[g], b[nt][0], b[nt][2]);
                    mma16816(acc[g][nt * 2 + 1], ahi[g], b[nt][1], b[nt][3]);
                    mma16816(acc[g][nt * 2 + 0], alo[g], b[nt][0], b[nt][2]);
                    mma16816(acc[g][nt * 2 + 1], alo[g], b[nt][1], b[nt][3]);
                }
            #pragma unroll
            for (int nt = 0; nt < 4; nt++) {
                const uint32_t ro = (uint32_t)((nbase + nt * 16 + rlane) * 128);
                ldsm_x4(sB + sw128(ro + 64 + kb), b[nt][0], b[nt][1], b[nt][2], b[nt][3]);
            }
            #pragma unroll
            for (int g = 0; g < 2; g++)
                #pragma unroll
                for (int nt = 0; nt < 4; nt++) {
                    mma16816(acc[g][nt * 2 + 0], ahi[g], b[nt][0], b[nt][2]);
                    mma16816(acc[g][nt * 2 + 1], ahi[g], b[nt][1], b[nt][3]);
                }
        }
        __syncthreads();
    }

    // ---- epilogue ----
    const int gq = lane >> 2;
    const int tq = lane & 3;
    #pragma unroll
    for (int g = 0; g < 2; g++) {
        const int row_lo = m0 + mbase + g * 16 + gq;
        const int row_hi = row_lo + 8;
        #pragma unroll
        for (int nt = 0; nt < 8; nt++) {
            const int col = nbase + nt * 8 + tq * 2;
            if (row_lo < N_NODES)
                *reinterpret_cast<float2*>(out + (size_t)row_lo * OUT_DIM + col) =
                    make_float2(acc[g][nt][0], acc[g][nt][1]);
            if (row_hi < N_NODES)
                *reinterpret_cast<float2*>(out + (size_t)row_hi * OUT_DIM + col) =
                    make_float2(acc[g][nt][2], acc[g][nt][3]);
        }
    }
}

// ---------------------------------------------------------------------------
// Launch
// ---------------------------------------------------------------------------
extern "C" void kernel_launch(void* const* d_in, const int* in_sizes, int n_in,
                              void* d_out, int out_size) {
    const float* x      = (const float*)d_in[0];
    const float* weight = (const float*)d_in[1];
    const float* selfw  = (const float*)d_in[2];
    const int*   ei     = (const int*)d_in[3];
    const int*   et     = (const int*)d_in[4];
    float*       out    = (float*)d_out;

    cudaFuncSetAttribute(gemm_kernel,
                         cudaFuncAttributeMaxDynamicSharedMemorySize, SMEM_TOTAL);

    zero_cnt_kernel<<<(R_REL * N_NODES + 255) / 256, 256>>>();
    convert_w_kernel<<<(OUT_DIM * K_DIM + 255) / 256, 256>>>(weight, selfw);
    fill_kernel<<<(E_EDGES + 255) / 256, 256>>>(ei, et);

    const int segs = N_NODES * 9;                       // 450000 warps
    agg_kernel<<<(segs + 7) / 8, 256>>>(x);

    gemm_kernel<<<(N_NODES + 127) / 128, 256, SMEM_TOTAL>>>(out);
}